// round 4
// baseline (speedup 1.0000x reference)
#include <cuda_runtime.h>

#define N_NODES 100000
#define E_EDGES 500000
#define H 128

// Precomputed per-node MLP partials:
//   C_x[row][0:128]   = z_x[row] @ w1[0:128, :]    (src contribution)
//   C_x[row][128:256] = z_x[row] @ w1[128:256, :]  (dst contribution)
__device__ float g_Cp[(size_t)N_NODES * 256];
__device__ float g_Co[(size_t)N_NODES * 256];

// ---------------------------------------------------------------------------
// Phase 1: node GEMMs.  grid = (ceil(M/128), 4), 256 threads.
// blockIdx.y: bit0 = w1 half (part), bit1 = table (0: pnode, 1: onode).
// Classic 128x128 fp32 register-blocked SGEMM, K = 128 in 4 chunks of 32.
// ---------------------------------------------------------------------------
__global__ __launch_bounds__(256, 2)
void node_gemm_kernel(const float* __restrict__ Zp,
                      const float* __restrict__ Zo,
                      const float* __restrict__ w1)
{
    const int part  = blockIdx.y & 1;   // which half of w1
    const int table = blockIdx.y >> 1;  // 0: pnode, 1: onode
    const float* __restrict__ Z = table ? Zo : Zp;
    float* __restrict__ C       = table ? g_Co : g_Cp;
    const float* __restrict__ W = w1 + (size_t)part * 128 * H;  // [128][128] row-major

    __shared__ float As[32][132];   // A^T tile: [k][m], padded
    __shared__ float Bs[32][128];   // B tile:   [k][n]

    const int tid = threadIdx.x;
    const int tx  = tid & 15;       // n-group
    const int ty  = tid >> 4;       // m-group
    const int m0  = blockIdx.x * 128;

    float acc[2][2][4][4];
#pragma unroll
    for (int a = 0; a < 2; a++)
#pragma unroll
        for (int b = 0; b < 2; b++)
#pragma unroll
            for (int r = 0; r < 4; r++)
#pragma unroll
                for (int c = 0; c < 4; c++)
                    acc[a][b][r][c] = 0.f;

    for (int kk = 0; kk < H; kk += 32) {
        // Load A tile (128 rows x 32 k) transposed into As[k][m]
#pragma unroll
        for (int i = 0; i < 4; i++) {
            int f4  = tid + 256 * i;        // 0..1023 float4 slots
            int row = f4 >> 3;              // 0..127
            int c4  = f4 & 7;               // 0..7 (k float4 within chunk)
            float4 v = make_float4(0.f, 0.f, 0.f, 0.f);
            if (m0 + row < N_NODES)
                v = *(const float4*)&Z[(size_t)(m0 + row) * H + kk + c4 * 4];
            As[c4 * 4 + 0][row] = v.x;
            As[c4 * 4 + 1][row] = v.y;
            As[c4 * 4 + 2][row] = v.z;
            As[c4 * 4 + 3][row] = v.w;
        }
        // Load B tile (32 k x 128 n)
#pragma unroll
        for (int i = 0; i < 4; i++) {
            int f4 = tid + 256 * i;         // 0..1023
            int k  = f4 >> 5;               // 0..31
            int n  = (f4 & 31) * 4;
            *(float4*)&Bs[k][n] = *(const float4*)&W[(size_t)(kk + k) * H + n];
        }
        __syncthreads();

#pragma unroll
        for (int k = 0; k < 32; k++) {
            float4 a0 = *(float4*)&As[k][ty * 4];
            float4 a1 = *(float4*)&As[k][ty * 4 + 64];
            float4 b0 = *(float4*)&Bs[k][tx * 4];
            float4 b1 = *(float4*)&Bs[k][tx * 4 + 64];
            float ar[2][4] = {{a0.x, a0.y, a0.z, a0.w}, {a1.x, a1.y, a1.z, a1.w}};
            float br[2][4] = {{b0.x, b0.y, b0.z, b0.w}, {b1.x, b1.y, b1.z, b1.w}};
#pragma unroll
            for (int im = 0; im < 2; im++)
#pragma unroll
                for (int r = 0; r < 4; r++)
#pragma unroll
                    for (int in = 0; in < 2; in++)
#pragma unroll
                        for (int c = 0; c < 4; c++)
                            acc[im][in][r][c] = fmaf(ar[im][r], br[in][c], acc[im][in][r][c]);
        }
        __syncthreads();
    }

    // Store: C[row][part*128 + n]
#pragma unroll
    for (int im = 0; im < 2; im++) {
#pragma unroll
        for (int r = 0; r < 4; r++) {
            int row = m0 + ty * 4 + r + im * 64;
            if (row < N_NODES) {
#pragma unroll
                for (int in = 0; in < 2; in++) {
                    float4 v = make_float4(acc[im][in][r][0], acc[im][in][r][1],
                                           acc[im][in][r][2], acc[im][in][r][3]);
                    *(float4*)&C[(size_t)row * 256 + part * 128 + tx * 4 + in * 64] = v;
                }
            }
        }
    }
}

// ---------------------------------------------------------------------------
// Phase 2: per-edge gather + relu + dot(w2).  One warp per edge.
// grid = (E/8, 3), 256 threads (8 warps/block). Edge types in y so each
// type's table working set stays mostly L2-resident while it runs.
// ---------------------------------------------------------------------------
__global__ __launch_bounds__(256)
void edge_kernel(const int* __restrict__ ptnp,
                 const int* __restrict__ nptp,
                 const int* __restrict__ nptnp,
                 const float* __restrict__ b1,
                 const float* __restrict__ w2,
                 const float* __restrict__ b2,
                 float* __restrict__ out)
{
    const int i    = blockIdx.x * 8 + (threadIdx.x >> 5);
    const int lane = threadIdx.x & 31;
    if (i >= E_EDGES) return;
    const int type = blockIdx.y;

    const float* __restrict__ src_tab;
    const float* __restrict__ dst_tab;
    const int* __restrict__ idx;
    if (type == 0) {            // ptnp: pnode -> onode
        idx = ptnp;  src_tab = g_Cp; dst_tab = g_Co;
    } else if (type == 1) {     // nptp: onode -> pnode
        idx = nptp;  src_tab = g_Co; dst_tab = g_Cp;
    } else {                    // nptnp: onode -> onode
        idx = nptnp; src_tab = g_Co; dst_tab = g_Co;
    }
    const int s = __ldg(&idx[i]);
    const int d = __ldg(&idx[E_EDGES + i]);
    const float bias2 = __ldg(b2);

    const float4 sv = *(const float4*)(src_tab + (size_t)s * 256 + lane * 4);
    const float4 dv = *(const float4*)(dst_tab + (size_t)d * 256 + 128 + lane * 4);
    const float4 bv = __ldg((const float4*)b1 + lane);
    const float4 wv = __ldg((const float4*)w2 + lane);

    float h0 = fmaxf(sv.x + dv.x + bv.x, 0.f);
    float h1 = fmaxf(sv.y + dv.y + bv.y, 0.f);
    float h2 = fmaxf(sv.z + dv.z + bv.z, 0.f);
    float h3 = fmaxf(sv.w + dv.w + bv.w, 0.f);

    float sum = h0 * wv.x + h1 * wv.y + h2 * wv.z + h3 * wv.w;
#pragma unroll
    for (int o = 16; o; o >>= 1)
        sum += __shfl_xor_sync(0xffffffffu, sum, o);

    if (lane == 0)
        out[(size_t)type * E_EDGES + i] = sum + bias2;
}

// ---------------------------------------------------------------------------
extern "C" void kernel_launch(void* const* d_in, const int* in_sizes, int n_in,
                              void* d_out, int out_size)
{
    const float* zp    = (const float*)d_in[0];
    const float* zo    = (const float*)d_in[1];
    const int*   ptnp  = (const int*)d_in[2];
    const int*   nptp  = (const int*)d_in[3];
    const int*   nptnp = (const int*)d_in[4];
    const float* w1    = (const float*)d_in[5];
    const float* b1    = (const float*)d_in[6];
    const float* w2    = (const float*)d_in[7];
    const float* b2    = (const float*)d_in[8];
    float* out = (float*)d_out;

    dim3 g1((N_NODES + 127) / 128, 4, 1);
    node_gemm_kernel<<<g1, 256>>>(zp, zo, w1);

    dim3 g2(E_EDGES / 8, 3, 1);
    edge_kernel<<<g2, 256>>>(ptnp, nptp, nptnp, b1, w2, b2, out);
}